// round 17
// baseline (speedup 1.0000x reference)
#include <cuda_runtime.h>
#include <cuda_bf16.h>
#include <math.h>
#include <cstdint>

#define HH 96
#define WW 96
#define HW (HH*WW)

// padded pixel-major bf16 tensor: [b][plane(hi/lo)][98*98 px][128 ch]
#define PLANE98 (9604*128)
#define PXB98   (2*PLANE98)

// ======================= helpers =======================
__device__ __forceinline__ uint32_t smem_u32(const void* p) {
    uint32_t a;
    asm("{ .reg .u64 t; cvta.to.shared.u64 t, %1; cvt.u32.u64 %0, t; }" : "=r"(a) : "l"(p));
    return a;
}
__device__ __forceinline__ void cp_async16(uint32_t saddr, const void* g) {
    asm volatile("cp.async.cg.shared.global [%0], [%1], 16;" :: "r"(saddr), "l"(g));
}
__device__ __forceinline__ void ldsm_x4(uint32_t* r, uint32_t a) {
    asm volatile("ldmatrix.sync.aligned.m8n8.x4.shared.b16 {%0,%1,%2,%3}, [%4];"
        : "=r"(r[0]), "=r"(r[1]), "=r"(r[2]), "=r"(r[3]) : "r"(a));
}
__device__ __forceinline__ void mma_bf16(float* c, const uint32_t* a, const uint32_t* b) {
    asm volatile("mma.sync.aligned.m16n8k16.row.col.f32.bf16.bf16.f32 "
        "{%0,%1,%2,%3}, {%4,%5,%6,%7}, {%8,%9}, {%0,%1,%2,%3};"
        : "+f"(c[0]), "+f"(c[1]), "+f"(c[2]), "+f"(c[3])
        : "r"(a[0]), "r"(a[1]), "r"(a[2]), "r"(a[3]), "r"(b[0]), "r"(b[1]));
}

// ======================= scratch globals =======================
__device__ float g_om[2*216*HW];                    // conv_om out (fp32 planar)
__device__ __align__(128) float g_R1px[2*HW*128];   // R1 pixel-major fp32
// padded px-major bf16 tensors (float-backed)
__device__ __align__(128) float g_din98[PXB98];
__device__ __align__(128) float g_t1b98[PXB98];
__device__ __align__(128) float g_t2b98[PXB98];
__device__ __align__(128) float g_q098 [PXB98];
__device__ __align__(128) float g_fea98[PXB98];
// packed conv weights: per (chunk,tap) block 20480 B: [hi 128co x 80B][lo same]
__device__ __align__(128) float g_wp1[36*5120];
__device__ __align__(128) float g_wp2[36*5120];
__device__ __align__(128) float g_wpom[72*5120];
__device__ __align__(128) float g_wprq[72*5120];
// packed DCN weights: per (g,k) block 12288 B: [hi 128co x 48B][lo at +6144]
__device__ __align__(128) float g_wtp[72*3072];

// ============================================================================
// Merged prep (500 blocks):
// 0-215 conv weight packs | 216-287 dcn wt | 288-479 merged transposes (b,y) |
// 480-499 border zero (5 tensors x b x plane)
// ============================================================================
__device__ __forceinline__ void pack_block(const float* __restrict__ w,
                                           float* __restrict__ dst,
                                           int CIN, int COUT, int co0,
                                           int cb, int tap, bool remap)
{
    char* d = (char*)dst;
    for (int e = threadIdx.x; e < 128*40; e += 256) {
        int co = e / 40;
        int cl = e - co * 40;
        float v = 0.f;
        if (cl < 32) {
            int src = co;
            bool ok;
            if (remap) {
                ok = (co & 31) < 24;
                src = (co >> 5) * 24 + (co & 31);
                ok = ok && (co0 + src) < COUT;
            } else {
                ok = (co0 + co) < COUT;
            }
            if (ok) v = w[((size_t)(co0 + src) * CIN + cb * 32 + cl) * 9 + tap];
        }
        __nv_bfloat16 hi = __float2bfloat16(v);
        __nv_bfloat16 lo = __float2bfloat16(v - __bfloat162float(hi));
        *(__nv_bfloat16*)(d +         co * 80 + cl * 2) = hi;
        *(__nv_bfloat16*)(d + 10240 + co * 80 + cl * 2) = lo;
    }
}

__device__ __forceinline__ void write_px98(float ts[64][97],
                                           __nv_bfloat16* __restrict__ dst,
                                           int b, int y, int half)
{
    for (int e = threadIdx.x; e < 96*64; e += 256) {
        int x  = e / 64;
        int ci = e - x * 64;
        float v = ts[ci][x];
        __nv_bfloat16 hi = __float2bfloat16(v);
        __nv_bfloat16 lo = __float2bfloat16(v - __bfloat162float(hi));
        size_t o = (size_t)b*PXB98 + (size_t)((y+1)*98 + (x+1))*128 + half*64 + ci;
        dst[o]           = hi;
        dst[o + PLANE98] = lo;
    }
}

__global__ void prepack_all_k(const float* __restrict__ R1,
                              const float* __restrict__ Q0,
                              const float* __restrict__ w1,
                              const float* __restrict__ w2,
                              const float* __restrict__ w_om,
                              const float* __restrict__ w_rq,
                              const float* __restrict__ w_dcn,
                              float* __restrict__ wp1, float* __restrict__ wp2,
                              float* __restrict__ wpom, float* __restrict__ wprq,
                              float* __restrict__ wtp,
                              __nv_bfloat16* __restrict__ din,
                              __nv_bfloat16* __restrict__ t1b,
                              __nv_bfloat16* __restrict__ t2b,
                              __nv_bfloat16* __restrict__ q0p,
                              __nv_bfloat16* __restrict__ feap,
                              float* __restrict__ r1px)
{
    __shared__ float ts[64][97];
    const int blk = blockIdx.x;
    if (blk < 36) {
        pack_block(w1, wp1 + (size_t)blk*5120, 128, 128, 0, blk/9, blk%9, false);
    } else if (blk < 72) {
        int b2 = blk - 36;
        pack_block(w2, wp2 + (size_t)b2*5120, 128, 128, 0, b2/9, b2%9, false);
    } else if (blk < 108) {
        int b2 = blk - 72;
        pack_block(w_om, wpom + (size_t)b2*5120, 128, 216, 0, b2/9, b2%9, false);
    } else if (blk < 144) {
        int b2 = blk - 108;
        pack_block(w_om, wpom + (size_t)(36 + b2)*5120, 128, 216, 128, b2/9, b2%9, true);
    } else if (blk < 216) {
        int b2 = blk - 144;
        pack_block(w_rq, wprq + (size_t)b2*5120, 256, 128, 0, b2/9, b2%9, false);
    } else if (blk < 288) {
        int b2 = blk - 216;
        int g = b2 / 9, k = b2 % 9;
        char* d = (char*)wtp + (size_t)b2 * 12288;
        for (int e = threadIdx.x; e < 2048; e += 256) {
            int co = e >> 4;
            int c  = e & 15;
            float v = w_dcn[(co*128 + g*16 + c)*9 + k];
            __nv_bfloat16 hi = __float2bfloat16(v);
            __nv_bfloat16 lo = __float2bfloat16(v - __bfloat162float(hi));
            *(__nv_bfloat16*)(d +        co * 48 + c * 2) = hi;
            *(__nv_bfloat16*)(d + 6144 + co * 48 + c * 2) = lo;
        }
    } else if (blk < 480) {
        // merged transposes: one (b,y) row -> r1px (fp32), din (R1-Q0), q0p (Q0)
        int tb = blk - 288;
        int b  = tb / 96;
        int y  = tb % 96;
        for (int half = 0; half < 2; half++) {
            // ts = R1
            for (int e = threadIdx.x; e < 64*96; e += 256) {
                int ci = e / 96;
                int x  = e - ci * 96;
                ts[ci][x] = R1[((size_t)(b*128 + half*64 + ci)*96 + y)*96 + x];
            }
            __syncthreads();
            // write r1px
            for (int e = threadIdx.x; e < 96*64; e += 256) {
                int x  = e / 64;
                int ci = e - x * 64;
                r1px[((size_t)b*HW + y*96 + x)*128 + half*64 + ci] = ts[ci][x];
            }
            __syncthreads();
            // ts -= Q0
            for (int e = threadIdx.x; e < 64*96; e += 256) {
                int ci = e / 96;
                int x  = e - ci * 96;
                ts[ci][x] -= Q0[((size_t)(b*128 + half*64 + ci)*96 + y)*96 + x];
            }
            __syncthreads();
            write_px98(ts, din, b, y, half);
            __syncthreads();
            // ts = Q0
            for (int e = threadIdx.x; e < 64*96; e += 256) {
                int ci = e / 96;
                int x  = e - ci * 96;
                ts[ci][x] = Q0[((size_t)(b*128 + half*64 + ci)*96 + y)*96 + x];
            }
            __syncthreads();
            write_px98(ts, q0p, b, y, half);
            __syncthreads();
        }
    } else {
        int idx = blk - 480;
        int tensor = idx >> 2;
        int b      = (idx >> 1) & 1;
        int plane  = idx & 1;
        uint32_t* dst = (uint32_t*)(tensor == 0 ? (void*)din :
                                    tensor == 1 ? (void*)t1b :
                                    tensor == 2 ? (void*)t2b :
                                    tensor == 3 ? (void*)q0p : (void*)feap);
        size_t base32 = ((size_t)b*PXB98 + (size_t)plane*PLANE98) >> 1;
        for (int e = threadIdx.x; e < 388*64; e += 256) {
            int pxi = e >> 6;
            int w   = e & 63;
            int y, x;
            if      (pxi < 98)  { y = 0;         x = pxi; }
            else if (pxi < 196) { y = 97;        x = pxi - 98; }
            else if (pxi < 292) { y = pxi-196+1; x = 0; }
            else                { y = pxi-292+1; x = 97; }
            dst[base32 + (size_t)(y*98 + x)*64 + w] = 0u;
        }
    }
}

// ============================================================================
// conv body (device function): 2-tap windows, 4-stage B ring.
// ============================================================================
#define SMA_BUF 16000
#define SMBX_OFF 32000
#define SMBX_ST  20480
#define CONVPX_SMEM (32000 + 4*20480)   // 113920

__device__ __forceinline__ void loadA98(uint32_t sbase, int buf,
                                        const __nv_bfloat16* __restrict__ tA,
                                        const __nv_bfloat16* __restrict__ tB,
                                        int cbn, int b, int x0, int y0, int tid)
{
    const __nv_bfloat16* t = (cbn < 4) ? tA : tB;
    const int cbc = (cbn < 4) ? cbn : cbn - 4;
    const uint32_t abase = sbase + (uint32_t)buf * SMA_BUF;
#pragma unroll
    for (int i = 0; i < 4; i++) {
        int e = tid + i*256;
        if (e < 800) {
            int plane = e >= 400;
            int rr  = e - plane*400;
            int px  = rr >> 2;
            int seg = rr & 3;
            int gy  = y0 + px / 10;
            int gx  = x0 + px % 10;
            const __nv_bfloat16* src = t + (size_t)b*PXB98 + (size_t)plane*PLANE98
                                     + (size_t)(gy*98 + gx)*128 + cbc*32 + seg*8;
            cp_async16(abase + (uint32_t)(plane*8000 + px*80 + seg*16), src);
        }
    }
}

__device__ __forceinline__ void loadB(uint32_t smB, const float* wpack, int it, int tid)
{
    const char* src = (const char*)wpack + (size_t)it * 20480;
    uint32_t dstb = smB + (uint32_t)(it & 3) * SMBX_ST;
#pragma unroll
    for (int i = 0; i < 5; i++)
        cp_async16(dstb + (uint32_t)(tid + i*256)*16u, src + (tid + i*256)*16);
}

template<bool RELU, int OUTFMT, int NNF>
__device__ __forceinline__ void conv_body(
    const __nv_bfloat16* __restrict__ inA,
    const __nv_bfloat16* __restrict__ inB,
    const float* __restrict__ wpack, const float* __restrict__ bias,
    float* __restrict__ out_f, __nv_bfloat16* __restrict__ out_b,
    int COUT, int co0, int nchunk, int b, int x0, int y0, uint32_t sbase)
{
    const int tid    = threadIdx.x;
    const int lane   = tid & 31;
    const int wid    = tid >> 5;
    const int warp_m = wid & 1;
    const int warp_n = wid >> 1;

    const uint32_t smB = sbase + SMBX_OFF;

    const int dyL  = (lane >> 3) & 1;
    const int xL   = lane & 7;
    const int kAL  = (lane & 16) ? 16 : 0;
    const uint32_t aoffL = (uint32_t)((dyL*10 + xL)*80 + kAL) + (uint32_t)warp_m*3200u;
    const int colL = (lane & 7) + ((lane & 16) ? 8 : 0);
    const int kBL  = (lane & 8) ? 16 : 0;
    const uint32_t boffL = (uint32_t)((warp_n*32 + colL)*80 + kBL);

    float acc[2][NNF][4];
#pragma unroll
    for (int i = 0; i < 2; i++)
#pragma unroll
        for (int j = 0; j < NNF; j++)
#pragma unroll
            for (int k = 0; k < 4; k++) acc[i][j][k] = 0.f;

    const int niter = nchunk * 9;
    const int nwin  = niter >> 1;

    loadA98(sbase, 0, inA, inB, 0, b, x0, y0, tid);
    loadB(smB, wpack, 0, tid);
    loadB(smB, wpack, 1, tid);
    asm volatile("cp.async.commit_group;");

    for (int w = 0; w < nwin; w++) {
        const int i0 = w * 2;

        asm volatile("cp.async.wait_group 0;");
        __syncthreads();

        if (i0 + 2 < niter) loadB(smB, wpack, i0 + 2, tid);
        if (i0 + 3 < niter) loadB(smB, wpack, i0 + 3, tid);
#pragma unroll
        for (int j = 0; j < 2; j++) {
            const int i = i0 + j;
            if (i % 9 == 2 && i / 9 + 1 < nchunk)
                loadA98(sbase, (i/9 + 1) & 1, inA, inB, i/9 + 1, b, x0, y0, tid);
        }
        asm volatile("cp.async.commit_group;");

#pragma unroll
        for (int j = 0; j < 2; j++) {
            const int i  = i0 + j;
            const int cb = i / 9;
            const int tap = i - cb * 9;
            const int ky = tap / 3, kx = tap % 3;
            const uint32_t abase  = sbase + (uint32_t)(cb & 1) * SMA_BUF;
            const uint32_t bstage = smB + (uint32_t)(i & 3) * SMBX_ST;
            const uint32_t atap   = abase + aoffL + (uint32_t)((ky*10 + kx)*80);

#pragma unroll
            for (int ks = 0; ks < 2; ks++) {
                uint32_t bh[2][4], bl[2][4];
#pragma unroll
                for (int nfp = 0; nfp < 2; nfp++) {
                    uint32_t ba = bstage + boffL + (uint32_t)(nfp*16*80 + ks*32);
                    ldsm_x4(bh[nfp], ba);
                    ldsm_x4(bl[nfp], ba + 10240u);
                }
#pragma unroll
                for (int mf = 0; mf < 2; mf++) {
                    uint32_t ar = atap + (uint32_t)(mf*1600 + ks*32);
                    uint32_t ah[4], al[4];
                    ldsm_x4(ah, ar);
                    ldsm_x4(al, ar + 8000u);
#pragma unroll
                    for (int nf = 0; nf < NNF; nf++) {
                        const uint32_t* bhp = &bh[nf >> 1][(nf & 1) * 2];
                        const uint32_t* blp = &bl[nf >> 1][(nf & 1) * 2];
                        mma_bf16(acc[mf][nf], ah, bhp);
                        mma_bf16(acc[mf][nf], ah, blp);
                        mma_bf16(acc[mf][nf], al, bhp);
                    }
                }
            }
        }
    }

    // ---- epilogue ----
    const int xr = lane >> 2;
#pragma unroll
    for (int nf = 0; nf < NNF; nf++) {
        int co_t = warp_n*32 + nf*8 + (lane & 3)*2;
        int co_a;
        if (NNF == 3) co_a = co0 + (co_t >> 5)*24 + (co_t & 31);
        else          co_a = co0 + co_t;
        const int co_b = co_a + 1;
        const float ba_ = (co_a < COUT) ? bias[co_a] : 0.f;
        const float bb_ = (co_b < COUT) ? bias[co_b] : 0.f;
#pragma unroll
        for (int mf = 0; mf < 2; mf++) {
            const int ya = y0 + warp_m*4 + mf*2;
            float v0 = acc[mf][nf][0] + ba_;
            float v1 = acc[mf][nf][1] + bb_;
            float v2 = acc[mf][nf][2] + ba_;
            float v3 = acc[mf][nf][3] + bb_;
            if (RELU) {
                v0 = fmaxf(v0, 0.f); v1 = fmaxf(v1, 0.f);
                v2 = fmaxf(v2, 0.f); v3 = fmaxf(v3, 0.f);
            }
            if (OUTFMT == 1) {
                size_t o1 = (size_t)b*PXB98
                          + (size_t)((ya+1)*98 + x0 + xr + 1)*128 + (co_a - co0);
                size_t o2 = o1 + 98*128;
                __nv_bfloat16 h0 = __float2bfloat16(v0);
                __nv_bfloat16 h1 = __float2bfloat16(v1);
                __nv_bfloat16 h2 = __float2bfloat16(v2);
                __nv_bfloat16 h3 = __float2bfloat16(v3);
                *(uint32_t*)&out_b[o1] = (uint32_t)*(uint16_t*)&h0 | ((uint32_t)*(uint16_t*)&h1 << 16);
                *(uint32_t*)&out_b[o2] = (uint32_t)*(uint16_t*)&h2 | ((uint32_t)*(uint16_t*)&h3 << 16);
                __nv_bfloat16 l0 = __float2bfloat16(v0 - __bfloat162float(h0));
                __nv_bfloat16 l1 = __float2bfloat16(v1 - __bfloat162float(h1));
                __nv_bfloat16 l2 = __float2bfloat16(v2 - __bfloat162float(h2));
                __nv_bfloat16 l3 = __float2bfloat16(v3 - __bfloat162float(h3));
                *(uint32_t*)&out_b[o1 + PLANE98] = (uint32_t)*(uint16_t*)&l0 | ((uint32_t)*(uint16_t*)&l1 << 16);
                *(uint32_t*)&out_b[o2 + PLANE98] = (uint32_t)*(uint16_t*)&l2 | ((uint32_t)*(uint16_t*)&l3 << 16);
            } else {
                if (co_a < COUT) {
                    out_f[((size_t)(b*COUT + co_a)*HH + ya    )*WW + x0 + xr] = v0;
                    out_f[((size_t)(b*COUT + co_a)*HH + ya + 1)*WW + x0 + xr] = v2;
                }
                if (co_b < COUT) {
                    out_f[((size_t)(b*COUT + co_b)*HH + ya    )*WW + x0 + xr] = v1;
                    out_f[((size_t)(b*COUT + co_b)*HH + ya + 1)*WW + x0 + xr] = v3;
                }
            }
        }
    }
}

template<bool RELU, int OUTFMT, int NNF>
__global__ __launch_bounds__(256, 2)
void convPX_k(const __nv_bfloat16* __restrict__ inA,
              const __nv_bfloat16* __restrict__ inB,
              const float* __restrict__ wpack, const float* __restrict__ bias,
              float* __restrict__ out_f, __nv_bfloat16* __restrict__ out_b,
              int COUT, int co0, int nchunk)
{
    extern __shared__ char sm[];
    conv_body<RELU, OUTFMT, NNF>(inA, inB, wpack, bias, out_f, out_b,
                                 COUT, co0, nchunk,
                                 blockIdx.z, blockIdx.x * 8, blockIdx.y * 8,
                                 smem_u32(sm));
}

// merged conv_om: z<2 -> tile0 (NNF=4), z>=2 -> tile1 (NNF=3, remapped)
__global__ __launch_bounds__(256, 2)
void convOM_k(const __nv_bfloat16* __restrict__ t2b,
              const float* __restrict__ wpom, const float* __restrict__ b_om,
              float* __restrict__ om)
{
    extern __shared__ char sm[];
    const uint32_t sbase = smem_u32(sm);
    const int x0 = blockIdx.x * 8;
    const int y0 = blockIdx.y * 8;
    if (blockIdx.z < 2) {
        conv_body<false, 0, 4>(t2b, t2b, wpom, b_om, om, nullptr,
                               216, 0, 4, blockIdx.z, x0, y0, sbase);
    } else {
        conv_body<false, 0, 3>(t2b, t2b, wpom + 36*5120, b_om, om, nullptr,
                               216, 128, 4, blockIdx.z - 2, x0, y0, sbase);
    }
}

// ============================================================================
// DCNv2: software-pipelined sampling + quad-shfl param dedup (R16-verbatim).
// ============================================================================
#define DCN_A_ST  6144
#define DCN_WT    12288
#define DCN_WT_ST 12288
#define DCN_SMEM  (12288 + 3*12288)   // 49152

__global__ __launch_bounds__(256, 2)
void dcnMMA_k(const float* __restrict__ R1px, const float* __restrict__ om,
              const float* __restrict__ wtp, const float* __restrict__ bias,
              __nv_bfloat16* __restrict__ feap)
{
    extern __shared__ char sm[];
    const int tid    = threadIdx.x;
    const int lane   = tid & 31;
    const int wid    = tid >> 5;
    const int warp_m = wid & 1;
    const int warp_n = wid >> 1;
    const int x0     = blockIdx.x * 8;
    const int y0     = blockIdx.y * 8;
    const int b      = blockIdx.z;

    const uint32_t sbase = smem_u32(sm);
    const uint32_t smWT  = sbase + DCN_WT;

    const int px_s = tid >> 2;
    const int cq   = tid & 3;
    const int hs   = y0 + (px_s >> 3);
    const int gxs  = x0 + (px_s & 7);
    const unsigned srcl = (unsigned)(lane & ~3);
    const int obase = (b*216)*HW + hs*WW + gxs;

    const uint32_t aoffL = (uint32_t)((lane & 15) * 48 + ((lane & 16) ? 16 : 0))
                         + (uint32_t)warp_m * (32*48);
    const int colL = (lane & 7) + ((lane & 16) ? 8 : 0);
    const int kBL  = (lane & 8) ? 16 : 0;
    const uint32_t boffL = (uint32_t)((warp_n*32 + colL)*48 + kBL);

    float acc[2][4][4];
#pragma unroll
    for (int i = 0; i < 2; i++)
#pragma unroll
        for (int j = 0; j < 4; j++)
#pragma unroll
            for (int k = 0; k < 4; k++) acc[i][j][k] = 0.f;

#pragma unroll
    for (int it = 0; it < 2; it++) {
        const char* src = (const char*)wtp + (size_t)it * 12288;
        uint32_t dstb = smWT + (uint32_t)it * DCN_WT_ST;
#pragma unroll
        for (int i = 0; i < 3; i++)
            cp_async16(dstb + (uint32_t)(tid + i*256)*16u, src + (tid + i*256)*16);
        asm volatile("cp.async.commit_group;");
    }

    float om_dy = 0.f, om_dx = 0.f, om_mr = 0.f;
    if (cq == 0) {
        om_dy = om[obase + (18*0 + 2*0    ) * HW];
        om_dx = om[obase + (18*0 + 2*0 + 1) * HW];
        om_mr = om[obase + (144 + 9*0 + 0 ) * HW];
    }

    // full sample(0) + STS stage 0
    {
        float w00, w01, w10, w11; int yi, xi;
        if (cq == 0) {
            float m  = 1.f / (1.f + __expf(-om_mr));
            float py  = om_dy + (float)(0 + hs - 1);
            float pxx = om_dx + (float)(0 + gxs - 1);
            float fy = floorf(py), fx = floorf(pxx);
            float ly = py - fy,  lx = pxx - fx;
            yi = (int)fy; xi = (int)fx;
            w00 = (1.f-ly)*(1.f-lx)*m; w01 = (1.f-ly)*lx*m;
            w10 = ly*(1.f-lx)*m;       w11 = ly*lx*m;
        }
        w00 = __shfl_sync(0xffffffffu, w00, srcl);
        w01 = __shfl_sync(0xffffffffu, w01, srcl);
        w10 = __shfl_sync(0xffffffffu, w10, srcl);
        w11 = __shfl_sync(0xffffffffu, w11, srcl);
        yi  = __shfl_sync(0xffffffffu, yi,  srcl);
        xi  = __shfl_sync(0xffffffffu, xi,  srcl);
        bool iy0 = (unsigned)yi < HH, iy1 = (unsigned)(yi+1) < HH;
        bool ix0 = (unsigned)xi < WW, ix1 = (unsigned)(xi+1) < WW;
        const float* pg = R1px + (size_t)b*HW*128 + 0*16 + cq*4;
        float4 z = make_float4(0.f,0.f,0.f,0.f);
        float4 a00 = (iy0&&ix0) ? *(const float4*)(pg + (size_t)(yi*WW+xi)*128)       : z;
        float4 a01 = (iy0&&ix1) ? *(const float4*)(pg + (size_t)(yi*WW+xi+1)*128)     : z;
        float4 a10 = (iy1&&ix0) ? *(const float4*)(pg + (size_t)((yi+1)*WW+xi)*128)   : z;
        float4 a11 = (iy1&&ix1) ? *(const float4*)(pg + (size_t)((yi+1)*WW+xi+1)*128) : z;
        float vv0 = w00*a00.x + w01*a01.x + w10*a10.x + w11*a11.x;
        float vv1 = w00*a00.y + w01*a01.y + w10*a10.y + w11*a11.y;
        float vv2 = w00*a00.z + w01*a01.z + w10*a10.z + w11*a11.z;
        float vv3 = w00*a00.w + w01*a01.w + w10*a10.w + w11*a11.w;
        __nv_bfloat16 h0=__float2bfloat16(vv0), h1=__float2bfloat16(vv1);
        __nv_bfloat16 h2=__float2bfloat16(vv2), h3=__float2bfloat16(vv3);
        uint32_t hp0 = (uint32_t)*(uint16_t*)&h0 | ((uint32_t)*(uint16_t*)&h1 << 16);
        uint32_t hp1 = (uint32_t)*(uint16_t*)&h2 | ((uint32_t)*(uint16_t*)&h3 << 16);
        __nv_bfloat16 l0=__float2bfloat16(vv0-__bfloat162float(h0));
        __nv_bfloat16 l1=__float2bfloat16(vv1-__bfloat162float(h1));
        __nv_bfloat16 l2=__float2bfloat16(vv2-__bfloat162float(h2));
        __nv_bfloat16 l3=__float2bfloat16(vv3-__bfloat162float(h3));
        uint32_t lp0 = (uint32_t)*(uint16_t*)&l0 | ((uint32_t)*(uint16_t*)&l1 << 16);
        uint32_t lp1 = (uint32_t)*(uint16_t*)&l2 | ((uint32_t)*(uint16_t*)&l3 << 16);
        *(uint2*)(sm +        px_s*48 + cq*8) = make_uint2(hp0, hp1);
        *(uint2*)(sm + 3072 + px_s*48 + cq*8) = make_uint2(lp0, lp1);
    }
    if (cq == 0) {
        om_dy = om[obase + (18*0 + 2*1    ) * HW];
        om_dx = om[obase + (18*0 + 2*1 + 1) * HW];
        om_mr = om[obase + (144 + 9*0 + 1 ) * HW];
    }

    for (int iter = 0; iter < 72; iter++) {
        float w00, w01, w10, w11;
        float4 a00, a01, a10, a11;
        const int in1 = iter + 1;
        if (in1 < 72) {
            const int g1 = in1 / 9;
            const int k1 = in1 - g1 * 9;
            int yi, xi;
            if (cq == 0) {
                float m  = 1.f / (1.f + __expf(-om_mr));
                float py  = om_dy + (float)(k1/3 + hs - 1);
                float pxx = om_dx + (float)(k1%3 + gxs - 1);
                float fy = floorf(py), fx = floorf(pxx);
                float ly = py - fy,  lx = pxx - fx;
                yi = (int)fy; xi = (int)fx;
                w00 = (1.f-ly)*(1.f-lx)*m; w01 = (1.f-ly)*lx*m;
                w10 = ly*(1.f-lx)*m;       w11 = ly*lx*m;
            }
            w00 = __shfl_sync(0xffffffffu, w00, srcl);
            w01 = __shfl_sync(0xffffffffu, w01, srcl);
            w10 = __shfl_sync(0xffffffffu, w10, srcl);
            w11 = __shfl_sync(0xffffffffu, w11, srcl);
            yi  = __shfl_sync(0xffffffffu, yi,  srcl);
            xi  = __shfl_sync(0xffffffffu, xi,  srcl);
            bool iy0 = (unsigned)yi < HH, iy1 = (unsigned)(yi+1) < HH;
            bool ix0 = (unsigned)xi < WW, ix1 = (unsigned)(xi+1) < WW;
            const float* pg = R1px + (size_t)b*HW*128 + g1*16 + cq*4;
            float4 z = make_float4(0.f,0.f,0.f,0.f);
            a00 = (iy0&&ix0) ? *(const float4*)(pg + (size_t)(yi*WW+xi)*128)       : z;
            a01 = (iy0&&ix1) ? *(const float4*)(pg + (size_t)(yi*WW+xi+1)*128)     : z;
            a10 = (iy1&&ix0) ? *(const float4*)(pg + (size_t)((yi+1)*WW+xi)*128)   : z;
            a11 = (iy1&&ix1) ? *(const float4*)(pg + (size_t)((yi+1)*WW+xi+1)*128) : z;
            const int in2 = iter + 2;
            if (in2 < 72 && cq == 0) {
                const int g2 = in2 / 9;
                const int k2 = in2 - g2 * 9;
                om_dy = om[obase + (18*g2 + 2*k2    ) * HW];
                om_dx = om[obase + (18*g2 + 2*k2 + 1) * HW];
                om_mr = om[obase + (144 + 9*g2 + k2 ) * HW];
            }
        }

        asm volatile("cp.async.wait_group 1;");
        __syncthreads();

        if (iter + 2 < 72) {
            const char* src = (const char*)wtp + (size_t)(iter + 2) * 12288;
            uint32_t dstb = smWT + (uint32_t)((iter + 2) % 3) * DCN_WT_ST;
#pragma unroll
            for (int i = 0; i < 3; i++)
                cp_async16(dstb + (uint32_t)(tid + i*256)*16u, src + (tid + i*256)*16);
        }
        asm volatile("cp.async.commit_group;");

        const uint32_t astage = sbase + (uint32_t)(iter & 1) * DCN_A_ST;
        const uint32_t wstage = smWT + (uint32_t)(iter % 3) * DCN_WT_ST;

        uint32_t bh[2][4], bl[2][4];
#pragma unroll
        for (int nfp = 0; nfp < 2; nfp++) {
            uint32_t ba = wstage + boffL + (uint32_t)(nfp*16*48);
            ldsm_x4(bh[nfp], ba);
            ldsm_x4(bl[nfp], ba + 6144u);
        }
#pragma unroll
        for (int mf = 0; mf < 2; mf++) {
            uint32_t ar = aoffL + astage + (uint32_t)(mf*16*48);
            uint32_t ah[4], al[4];
            ldsm_x4(ah, ar);
            ldsm_x4(al, ar + 3072u);
#pragma unroll
            for (int nf = 0; nf < 4; nf++) {
                const uint32_t* bhp = &bh[nf >> 1][(nf & 1) * 2];
                const uint32_t* blp = &bl[nf >> 1][(nf & 1) * 2];
                mma_bf16(acc[mf][nf], ah, bhp);
                mma_bf16(acc[mf][nf], ah, blp);
                mma_bf16(acc[mf][nf], al, bhp);
            }
        }

        if (in1 < 72) {
            float vv0 = w00*a00.x + w01*a01.x + w10*a10.x + w11*a11.x;
            float vv1 = w00*a00.y + w01*a01.y + w10*a10.y + w11*a11.y;
            float vv2 = w00*a00.z + w01*a01.z + w10*a10.z + w11*a11.z;
            float vv3 = w00*a00.w + w01*a01.w + w10*a10.w + w11*a11.w;
            __nv_bfloat16 h0=__float2bfloat16(vv0), h1=__float2bfloat16(vv1);
            __nv_bfloat16 h2=__float2bfloat16(vv2), h3=__float2bfloat16(vv3);
            uint32_t hp0 = (uint32_t)*(uint16_t*)&h0 | ((uint32_t)*(uint16_t*)&h1 << 16);
            uint32_t hp1 = (uint32_t)*(uint16_t*)&h2 | ((uint32_t)*(uint16_t*)&h3 << 16);
            __nv_bfloat16 l0=__float2bfloat16(vv0-__bfloat162float(h0));
            __nv_bfloat16 l1=__float2bfloat16(vv1-__bfloat162float(h1));
            __nv_bfloat16 l2=__float2bfloat16(vv2-__bfloat162float(h2));
            __nv_bfloat16 l3=__float2bfloat16(vv3-__bfloat162float(h3));
            uint32_t lp0 = (uint32_t)*(uint16_t*)&l0 | ((uint32_t)*(uint16_t*)&l1 << 16);
            uint32_t lp1 = (uint32_t)*(uint16_t*)&l2 | ((uint32_t)*(uint16_t*)&l3 << 16);
            char* asb = sm + (in1 & 1) * DCN_A_ST;
            *(uint2*)(asb +        px_s*48 + cq*8) = make_uint2(hp0, hp1);
            *(uint2*)(asb + 3072 + px_s*48 + cq*8) = make_uint2(lp0, lp1);
        }
    }

    // ---- epilogue: bias + relu -> padded px-major bf16 hi/lo ----
    const int r0 = warp_m*32 + (lane >> 2);
#pragma unroll
    for (int nf = 0; nf < 4; nf++) {
        const int co_a = warp_n*32 + nf*8 + (lane & 3)*2;
        const float ba_ = bias[co_a];
        const float bb_ = bias[co_a + 1];
#pragma unroll
        for (int mf = 0; mf < 2; mf++) {
            const int p1 = r0 + mf*16;
            const int p2 = p1 + 8;
            const int y1 = y0 + (p1 >> 3), x1 = x0 + (p1 & 7);
            const int y2 = y0 + (p2 >> 3), x2 = x0 + (p2 & 7);
            float v0 = fmaxf(acc[mf][nf][0] + ba_, 0.f);
            float v1 = fmaxf(acc[mf][nf][1] + bb_, 0.f);
            float v2 = fmaxf(acc[mf][nf][2] + ba_, 0.f);
            float v3 = fmaxf(acc[mf][nf][3] + bb_, 0.f);
            size_t o1 = (size_t)b*PXB98 + (size_t)((y1+1)*98 + x1 + 1)*128 + co_a;
            size_t o2 = (size_t)b*PXB98 + (size_t)((y2+1)*98 + x2 + 1)*128 + co_a;
            __nv_bfloat16 h0 = __float2bfloat16(v0);
            __nv_bfloat16 h1 = __float2bfloat16(v1);
            __nv_bfloat16 h2 = __float2bfloat16(v2);
            __nv_bfloat16 h3 = __float2bfloat16(v3);
            *(uint32_t*)&feap[o1] = (uint32_t)*(uint16_t*)&h0 | ((uint32_t)*(uint16_t*)&h1 << 16);
            *(uint32_t*)&feap[o2] = (uint32_t)*(uint16_t*)&h2 | ((uint32_t)*(uint16_t*)&h3 << 16);
            __nv_bfloat16 l0 = __float2bfloat16(v0 - __bfloat162float(h0));
            __nv_bfloat16 l1 = __float2bfloat16(v1 - __bfloat162float(h1));
            __nv_bfloat16 l2 = __float2bfloat16(v2 - __bfloat162float(h2));
            __nv_bfloat16 l3 = __float2bfloat16(v3 - __bfloat162float(h3));
            *(uint32_t*)&feap[o1 + PLANE98] = (uint32_t)*(uint16_t*)&l0 | ((uint32_t)*(uint16_t*)&l1 << 16);
            *(uint32_t*)&feap[o2 + PLANE98] = (uint32_t)*(uint16_t*)&l2 | ((uint32_t)*(uint16_t*)&l3 << 16);
        }
    }
}

// ============================================================================
extern "C" void kernel_launch(void* const* d_in, const int* in_sizes, int n_in,
                              void* d_out, int out_size)
{
    (void)in_sizes; (void)n_in; (void)out_size;
    const float* R1    = (const float*)d_in[0];
    const float* Q0    = (const float*)d_in[1];
    const float* w1    = (const float*)d_in[2];
    const float* b1    = (const float*)d_in[3];
    const float* w2    = (const float*)d_in[4];
    const float* b2    = (const float*)d_in[5];
    const float* w_om  = (const float*)d_in[6];
    const float* b_om  = (const float*)d_in[7];
    const float* w_dcn = (const float*)d_in[8];
    const float* b_dcn = (const float*)d_in[9];
    const float* w_rq  = (const float*)d_in[10];
    const float* b_rq  = (const float*)d_in[11];
    float* out = (float*)d_out;

    float *om, *wp1, *wp2, *wpom, *wprq, *wtp, *dinf, *t1f, *t2f, *q0f, *feaf, *r1px;
    cudaGetSymbolAddress((void**)&om,   g_om);
    cudaGetSymbolAddress((void**)&wp1,  g_wp1);
    cudaGetSymbolAddress((void**)&wp2,  g_wp2);
    cudaGetSymbolAddress((void**)&wpom, g_wpom);
    cudaGetSymbolAddress((void**)&wprq, g_wprq);
    cudaGetSymbolAddress((void**)&wtp,  g_wtp);
    cudaGetSymbolAddress((void**)&dinf, g_din98);
    cudaGetSymbolAddress((void**)&t1f,  g_t1b98);
    cudaGetSymbolAddress((void**)&t2f,  g_t2b98);
    cudaGetSymbolAddress((void**)&q0f,  g_q098);
    cudaGetSymbolAddress((void**)&feaf, g_fea98);
    cudaGetSymbolAddress((void**)&r1px, g_R1px);
    __nv_bfloat16* din  = (__nv_bfloat16*)dinf;
    __nv_bfloat16* t1b  = (__nv_bfloat16*)t1f;
    __nv_bfloat16* t2b  = (__nv_bfloat16*)t2f;
    __nv_bfloat16* q0p  = (__nv_bfloat16*)q0f;
    __nv_bfloat16* feap = (__nv_bfloat16*)feaf;

    cudaFuncSetAttribute(convPX_k<true ,1,4>, cudaFuncAttributeMaxDynamicSharedMemorySize, CONVPX_SMEM);
    cudaFuncSetAttribute(convPX_k<true ,0,4>, cudaFuncAttributeMaxDynamicSharedMemorySize, CONVPX_SMEM);
    cudaFuncSetAttribute(convOM_k, cudaFuncAttributeMaxDynamicSharedMemorySize, CONVPX_SMEM);
    cudaFuncSetAttribute(dcnMMA_k, cudaFuncAttributeMaxDynamicSharedMemorySize, DCN_SMEM);

    // all prep in one launch
    prepack_all_k<<<500, 256>>>(R1, Q0, w1, w2, w_om, w_rq, w_dcn,
                                wp1, wp2, wpom, wprq, wtp,
                                din, t1b, t2b, q0p, feap, r1px);

    // conv1: relu(conv(R1-Q0)) -> t1 (px-major bf16)
    convPX_k<true ,1,4><<<dim3(12,12,2), 256, CONVPX_SMEM>>>(din, din, wp1, b1, nullptr, t1b, 128, 0, 4);
    // conv2: relu(conv(t1)) -> t2 (px-major bf16)
    convPX_k<true ,1,4><<<dim3(12,12,2), 256, CONVPX_SMEM>>>(t1b, t1b, wp2, b2, nullptr, t2b, 128, 0, 4);
    // conv_om: both co tiles in ONE launch (z<2: co 0-127; z>=2: co 128-215 remapped)
    convOM_k<<<dim3(12,12,4), 256, CONVPX_SMEM>>>(t2b, wpom, b_om, om);
    // deformable conv v2 + relu -> fea (px-major bf16)
    dcnMMA_k<<<dim3(12,12,2), 256, DCN_SMEM>>>(r1px, om, wtp, b_dcn, feap);
    // conv_rq: relu(conv(concat(fea, Q0))) -> out (fp32 planar)
    convPX_k<true ,0,4><<<dim3(12,12,2), 256, CONVPX_SMEM>>>(feap, q0p, wprq, b_rq, out, nullptr, 128, 0, 8);
}